// round 1
// baseline (speedup 1.0000x reference)
#include <cuda_runtime.h>
#include <math_constants.h>

// CRF neg-log-likelihood on GB300.
// Strategy: per-batch CTA (64 CTAs), linear-space forward recursion with
// running log-offset. exp(transitions) cached in registers (one column per
// thread). Per step: 50-FFMA GEMV + 1 EX2, rescale every 4 steps.

namespace {
constexpr int NTAG  = 50;
constexpr int TSTART = NTAG - 2;  // 48
constexpr int TSTOP  = NTAG - 1;  // 49
constexpr int BATCH = 64;
constexpr int SEQ   = 512;
constexpr int NTHR  = 64;   // threads per block (2 warps)
constexpr int NPAD  = 52;   // 50 padded to multiple of 4 for float4 loads
}

__device__ float g_partial[BATCH];

__device__ __forceinline__ float warpMaxF(float v) {
#pragma unroll
    for (int o = 16; o > 0; o >>= 1)
        v = fmaxf(v, __shfl_xor_sync(0xffffffffu, v, o));
    return v;
}
__device__ __forceinline__ float warpSumF(float v) {
#pragma unroll
    for (int o = 16; o > 0; o >>= 1)
        v += __shfl_xor_sync(0xffffffffu, v, o);
    return v;
}
__device__ __forceinline__ int warpSumI(int v) {
#pragma unroll
    for (int o = 16; o > 0; o >>= 1)
        v += __shfl_xor_sync(0xffffffffu, v, o);
    return v;
}

__global__ void __launch_bounds__(NTHR, 1)
crf_fwd_kernel(const float* __restrict__ feats,
               const int*   __restrict__ mask,
               const int*   __restrict__ tags,
               const float* __restrict__ trans)
{
    const int b    = blockIdx.x;
    const int j    = threadIdx.x;
    const int lane = j & 31;
    const int wid  = j >> 5;
    const bool act = (j < NTAG);

    __shared__ __align__(16) float sp[2][NPAD];  // ping-pong partition (linear space)
    __shared__ float s_red[2];
    __shared__ float s_acc[2];
    __shared__ int   s_len[2];
    __shared__ int   s_mask[SEQ];
    __shared__ float s_fwd;

    const float* fb = feats + (long long)b * SEQ * NTAG;
    const int*   mb = mask  + b * SEQ;
    const int*   tb = tags  + b * SEQ;

    // preload mask bits for this batch row
    for (int t = j; t < SEQ; t += NTHR) s_mask[t] = mb[t];

    // exp(transitions) column j into registers (thread j owns next-tag j)
    float et[NPAD];
    et[50] = 0.f; et[51] = 0.f;
    if (act) {
#pragma unroll
        for (int i = 0; i < NTAG; i++) et[i] = __expf(trans[i * NTAG + j]);
    } else {
#pragma unroll
        for (int i = 0; i < NTAG; i++) et[i] = 0.f;
    }

    // ---- t = 0: partition0[j] = feats[b,0,j] + trans[START,j] ----
    float part0 = act ? (fb[j] + trans[TSTART * NTAG + j]) : -CUDART_INF_F;
    // block max
    float mv = warpMaxF(part0);
    if (lane == 0) s_red[wid] = mv;
    __syncthreads();                         // also covers s_mask writes
    float mx = fmaxf(s_red[0], s_red[1]);
    __syncthreads();
    float offset = mx;
    float p0 = act ? __expf(part0 - mx) : 0.f;
    if (j < NPAD) sp[0][j] = p0;             // j=50,51 write 0
    __syncthreads();

    // ---- scan over t = 1..S-1 ----
    float f0 = act ? fb[1 * NTAG + j] : 0.f;                 // feat for t=1
    float f1 = act ? fb[2 * NTAG + j] : 0.f;                 // feat for t=2
    int cur = 0;

    for (int t = 1; t < SEQ; t++) {
        float f = f0;
        f0 = f1;
        f1 = (act && (t + 2) < SEQ) ? fb[(t + 2) * NTAG + j] : 0.f;  // prefetch 2 ahead

        const int m = s_mask[t];
        float q = 0.f;
        if (act) {
            const float4* sp4 = (const float4*)sp[cur];
            float a0 = 0.f, a1 = 0.f, a2 = 0.f, a3 = 0.f;
#pragma unroll
            for (int k = 0; k < 13; k++) {
                float4 v = sp4[k];
                a0 = fmaf(v.x, et[4 * k + 0], a0);
                a1 = fmaf(v.y, et[4 * k + 1], a1);
                a2 = fmaf(v.z, et[4 * k + 2], a2);
                a3 = fmaf(v.w, et[4 * k + 3], a3);
            }
            float efeat = __expf(f);
            q = ((a0 + a1) + (a2 + a3)) * efeat;
            if (!m) q = sp[cur][j];          // masked step: partition unchanged
        }

        if ((t & 3) == 0) {
            // rescale every 4 steps to prevent fp32 overflow; adjust offset
            float w = warpMaxF(q);
            if (lane == 0) s_red[wid] = w;
            __syncthreads();
            float mq = fmaxf(s_red[0], s_red[1]);
            __syncthreads();
            q *= (1.0f / mq);
            offset += __logf(mq);
        }

        cur ^= 1;
        if (j < NPAD) sp[cur][j] = q;        // inactive threads write 0 pad
        __syncthreads();
    }

    // ---- terminal: forward_b = log(sum_i p[i]*exp(trans[i,STOP])) + offset ----
    if (j == TSTOP) {
        const float4* sp4 = (const float4*)sp[cur];
        float a0 = 0.f, a1 = 0.f, a2 = 0.f, a3 = 0.f;
#pragma unroll
        for (int k = 0; k < 13; k++) {
            float4 v = sp4[k];
            a0 = fmaf(v.x, et[4 * k + 0], a0);
            a1 = fmaf(v.y, et[4 * k + 1], a1);
            a2 = fmaf(v.z, et[4 * k + 2], a2);
            a3 = fmaf(v.w, et[4 * k + 3], a3);
        }
        float s = (a0 + a1) + (a2 + a3);
        s_fwd = __logf(s) + offset;
    }
    __syncthreads();

    // ---- gold score for this batch row ----
    float acc = 0.f;
    int   len = 0;
    for (int t = j; t < SEQ; t += NTHR) {
        int tag  = tb[t];
        int prev = (t == 0) ? TSTART : tb[t - 1];
        int m    = s_mask[t];
        if (m) acc += fb[t * NTAG + tag] + trans[prev * NTAG + tag];
        len += m;
    }
    acc = warpSumF(acc);
    len = warpSumI(len);
    if (lane == 0) { s_acc[wid] = acc; s_len[wid] = len; }
    __syncthreads();
    if (j == 0) {
        float gacc = s_acc[0] + s_acc[1];
        int   L    = s_len[0] + s_len[1];
        int   endid = tb[L - 1];
        float gold = gacc + trans[endid * NTAG + TSTOP];
        g_partial[b] = s_fwd - gold;
    }
}

__global__ void __launch_bounds__(NTHR, 1)
crf_reduce_kernel(float* __restrict__ out)
{
    const int j = threadIdx.x;
    __shared__ float s[2];
    float v = g_partial[j];
    v = warpSumF(v);
    if ((j & 31) == 0) s[j >> 5] = v;
    __syncthreads();
    if (j == 0) out[0] = s[0] + s[1];
}

extern "C" void kernel_launch(void* const* d_in, const int* in_sizes, int n_in,
                              void* d_out, int out_size)
{
    const float* feats = (const float*)d_in[0];
    const int*   mask  = (const int*)d_in[1];
    const int*   tags  = (const int*)d_in[2];
    const float* trans = (const float*)d_in[3];
    float* out = (float*)d_out;

    crf_fwd_kernel<<<BATCH, NTHR>>>(feats, mask, tags, trans);
    crf_reduce_kernel<<<1, NTHR>>>(out);
}

// round 2
// speedup vs baseline: 1.7451x; 1.7451x over previous
#include <cuda_runtime.h>
#include <cuda_bf16.h>
#include <math_constants.h>

// CRF neg-log-likelihood, GB300 sm_103a.
// 64 CTAs (one per batch row), 128 threads:
//   warps 0-1: linear-space forward recursion, partition in bf16, GEMV via HFMA2,
//              running log-offset, rescale by p_prev[0] every 4 steps (no reductions).
//   warps 2-3: gold score (emissions + transitions along the gold path).
// Last CTA to finish reduces the 64 per-batch values (atomic ticket) -> single kernel.

namespace {
constexpr int NTAG   = 50;
constexpr int TSTART = NTAG - 2;   // 48
constexpr int TSTOP  = NTAG - 1;   // 49
constexpr int BATCH  = 64;
constexpr int SEQ    = 512;
constexpr int NTHR   = 128;
constexpr int NPAIR  = 28;         // bf162 pairs per buffer (56 bf16: 50 + 6 zero pad)
}

__device__ float    g_partial[BATCH];
__device__ unsigned g_ticket = 0;

#define NAMED_BAR_FWD() asm volatile("bar.sync 1, 64;" ::: "memory")

__device__ __forceinline__ float warpSumF(float v) {
#pragma unroll
    for (int o = 16; o > 0; o >>= 1) v += __shfl_xor_sync(0xffffffffu, v, o);
    return v;
}
__device__ __forceinline__ int warpSumI(int v) {
#pragma unroll
    for (int o = 16; o > 0; o >>= 1) v += __shfl_xor_sync(0xffffffffu, v, o);
    return v;
}
__device__ __forceinline__ __nv_bfloat162 asbf2(float f) {
    return *reinterpret_cast<__nv_bfloat162*>(&f);
}

__global__ void __launch_bounds__(NTHR, 1)
crf_kernel(const float* __restrict__ feats,
           const int*   __restrict__ mask,
           const int*   __restrict__ tags,
           const float* __restrict__ trans,
           float*       __restrict__ out)
{
    const int b   = blockIdx.x;
    const int tid = threadIdx.x;
    const int wid = tid >> 5;

    __shared__ __align__(16) __nv_bfloat162 sp[2][NPAIR];  // ping-pong partition (linear)
    __shared__ float s_fwd;
    __shared__ float s_acc[2];
    __shared__ int   s_len[2];
    __shared__ int   s_mask[SEQ];
    __shared__ bool  s_last;
    __shared__ float s_red2[2];

    const float* fb = feats + (long long)b * SEQ * NTAG;
    const int*   mb = mask  + b * SEQ;
    const int*   tb = tags  + b * SEQ;

    if (wid < 2) {
        // ================= forward recursion (warps 0-1, 64 threads) =================
        const int  j   = tid;
        const bool act = (j < NTAG);

        // mask bits to smem
        for (int t = j; t < SEQ; t += 64) s_mask[t] = mb[t];

        // exp(transitions) column j as bf162 pairs (thread j owns next-tag j)
        __nv_bfloat162 et2[NPAIR];
#pragma unroll
        for (int k = 0; k < NPAIR; k++) et2[k] = __floats2bfloat162_rn(0.f, 0.f);
        if (act) {
#pragma unroll
            for (int k = 0; k < 25; k++) {
                float e0 = __expf(trans[(2 * k)     * NTAG + j]);
                float e1 = __expf(trans[(2 * k + 1) * NTAG + j]);
                et2[k] = __floats2bfloat162_rn(e0, e1);
            }
        }

        // t=0: normalize by partition0[tag 0] (computable per-thread, no reduction)
        const float off0   = fb[0] + trans[TSTART * NTAG + 0];
        float       offset = off0;
        float pj = 0.f;
        if (act) pj = __expf(fb[j] + trans[TSTART * NTAG + j] - off0);
        if (j < 2 * NPAIR) {
            ((__nv_bfloat16*)sp[0])[j] = __float2bfloat16(act ? pj : 0.f);
            ((__nv_bfloat16*)sp[1])[j] = __float2bfloat16(0.f);      // zero pads once
        }
        NAMED_BAR_FWD();

        // feat prefetch pipeline (depth 3)
        float f0 = act ? fb[1 * NTAG + j] : 0.f;
        float f1 = act ? fb[2 * NTAG + j] : 0.f;
        float f2 = act ? fb[3 * NTAG + j] : 0.f;
        int cur = 0;

#pragma unroll 4
        for (int t = 1; t < SEQ; t++) {
            const float f = f0;
            f0 = f1; f1 = f2;
            f2 = (act && (t + 3) < SEQ) ? fb[(t + 3) * NTAG + j] : 0.f;

            const float4* sp4 = (const float4*)sp[cur];
            __nv_bfloat162 a0 = __floats2bfloat162_rn(0.f, 0.f);
            __nv_bfloat162 a1 = a0, a2 = a0, a3 = a0;
            float p0f = 1.f;
#pragma unroll
            for (int k = 0; k < 7; k++) {
                float4 v = sp4[k];
                __nv_bfloat162 h0 = asbf2(v.x);
                __nv_bfloat162 h1 = asbf2(v.y);
                __nv_bfloat162 h2 = asbf2(v.z);
                __nv_bfloat162 h3 = asbf2(v.w);
                if (k == 0) p0f = __low2float(h0);   // p_prev[0]
                a0 = __hfma2(h0, et2[4 * k + 0], a0);
                a1 = __hfma2(h1, et2[4 * k + 1], a1);
                a2 = __hfma2(h2, et2[4 * k + 2], a2);
                a3 = __hfma2(h3, et2[4 * k + 3], a3);
            }
            a0 = __hadd2(a0, a1);
            a2 = __hadd2(a2, a3);
            a0 = __hadd2(a0, a2);
            float s  = __low2float(a0) + __high2float(a0);
            float q  = s * __expf(f);

            const int m = s_mask[t];
            q = m ? q : pj;                          // masked step: carry previous

            if ((t & 3) == 0) {                      // cheap rescale: divide by p_prev[0]
                q *= __frcp_rn(p0f);
                offset += __logf(p0f);
            }

            pj = q;
            cur ^= 1;
            if (act) ((__nv_bfloat16*)sp[cur])[j] = __float2bfloat16(q);
            NAMED_BAR_FWD();
        }

        // terminal: forward = log( sum_i p[i] * exp(trans[i,STOP]) ) + offset
        if (j == TSTOP) {
            const float4* sp4 = (const float4*)sp[cur];
            __nv_bfloat162 a0 = __floats2bfloat162_rn(0.f, 0.f);
            __nv_bfloat162 a1 = a0, a2 = a0, a3 = a0;
#pragma unroll
            for (int k = 0; k < 7; k++) {
                float4 v = sp4[k];
                a0 = __hfma2(asbf2(v.x), et2[4 * k + 0], a0);
                a1 = __hfma2(asbf2(v.y), et2[4 * k + 1], a1);
                a2 = __hfma2(asbf2(v.z), et2[4 * k + 2], a2);
                a3 = __hfma2(asbf2(v.w), et2[4 * k + 3], a3);
            }
            a0 = __hadd2(a0, a1);
            a2 = __hadd2(a2, a3);
            a0 = __hadd2(a0, a2);
            float s = __low2float(a0) + __high2float(a0);
            s_fwd = __logf(s) + offset;
        }
    } else {
        // ================= gold score (warps 2-3, 64 threads) =================
        const int gt = tid - 64;
        float acc = 0.f;
        int   len = 0;
        for (int t = gt; t < SEQ; t += 64) {
            int tag  = tb[t];
            int prev = (t == 0) ? TSTART : tb[t - 1];
            int m    = mb[t];
            if (m) acc += fb[t * NTAG + tag] + trans[prev * NTAG + tag];
            len += m;
        }
        acc = warpSumF(acc);
        len = warpSumI(len);
        if ((tid & 31) == 0) { s_acc[wid - 2] = acc; s_len[wid - 2] = len; }
    }

    __syncthreads();

    if (tid == 0) {
        int   L     = s_len[0] + s_len[1];
        int   endid = tb[L - 1];
        float gold  = s_acc[0] + s_acc[1] + trans[endid * NTAG + TSTOP];
        g_partial[b] = s_fwd - gold;
        __threadfence();
        unsigned tk = atomicAdd(&g_ticket, 1u);
        s_last = (tk == BATCH - 1);
    }
    __syncthreads();

    // last CTA out reduces all 64 batch values and resets the ticket
    if (s_last) {
        if (tid < BATCH) {
            float v = ((volatile float*)g_partial)[tid];
            v = warpSumF(v);
            if ((tid & 31) == 0) s_red2[tid >> 5] = v;
        }
        __syncthreads();
        if (tid == 0) {
            out[0] = s_red2[0] + s_red2[1];
            g_ticket = 0;                    // deterministic across graph replays
        }
    }
}

extern "C" void kernel_launch(void* const* d_in, const int* in_sizes, int n_in,
                              void* d_out, int out_size)
{
    const float* feats = (const float*)d_in[0];
    const int*   mask  = (const int*)d_in[1];
    const int*   tags  = (const int*)d_in[2];
    const float* trans = (const float*)d_in[3];
    float* out = (float*)d_out;

    crf_kernel<<<BATCH, NTHR>>>(feats, mask, tags, trans, out);
}

// round 3
// speedup vs baseline: 1.8856x; 1.0805x over previous
#include <cuda_runtime.h>
#include <cuda_bf16.h>
#include <math_constants.h>

// CRF neg-log-likelihood, GB300 sm_103a.
// 64 CTAs x 64 threads (2 warps; nw=2 => BAR.SYNC floor = 7 cyc).
// Linear-space forward recursion, partition in bf16 smem (ping-pong), GEMV via
// HFMA2 (thread j owns next-tag j), running log-offset, rescale by p_prev[0]
// every 4 steps. exp(feat) pipelined one step ahead of use (MUFU hidden).
// Gold score as epilogue in same CTA; last CTA reduces the batch (atomic ticket).

namespace {
constexpr int NTAG   = 50;
constexpr int TSTART = NTAG - 2;   // 48
constexpr int TSTOP  = NTAG - 1;   // 49
constexpr int BATCH  = 64;
constexpr int SEQ    = 512;
constexpr int NTHR   = 64;
constexpr int NPAIR  = 28;         // bf162 pairs (56 slots: 50 + 6 zero pad)
}

__device__ float    g_partial[BATCH];
__device__ unsigned g_ticket = 0;

__device__ __forceinline__ float warpSumF(float v) {
#pragma unroll
    for (int o = 16; o > 0; o >>= 1) v += __shfl_xor_sync(0xffffffffu, v, o);
    return v;
}
__device__ __forceinline__ int warpSumI(int v) {
#pragma unroll
    for (int o = 16; o > 0; o >>= 1) v += __shfl_xor_sync(0xffffffffu, v, o);
    return v;
}
__device__ __forceinline__ __nv_bfloat162 asbf2(float f) {
    return *reinterpret_cast<__nv_bfloat162*>(&f);
}

// One recursion step. src/dst are the ping-pong partition buffers.
template <bool RESCALE>
__device__ __forceinline__ void fwd_step(
    int t, int j, bool act,
    const __nv_bfloat162* __restrict__ src,
    __nv_bfloat162*       __restrict__ dst,
    const __nv_bfloat162* __restrict__ et2,
    float& ef, float& fr1, float& fr2, float& fr3,
    float& pj, float& offset,
    const float* __restrict__ fb,
    const int*   __restrict__ s_mask)
{
    // prefetch raw feat (t+4) and exponentiate feat (t+1) for the next step
    float frN = 0.f;
    if (act && (t + 4) < SEQ) frN = fb[(t + 4) * NTAG + j];
    float ef_next = __expf(fr1);

    const int m = s_mask[t];

    // issue all partition loads up front (broadcast, conflict-free)
    const float4* sp4 = (const float4*)src;
    float4 v0 = sp4[0];
    float4 v1 = sp4[1];
    float4 v2 = sp4[2];
    float4 v3 = sp4[3];
    float4 v4 = sp4[4];
    float4 v5 = sp4[5];
    float4 v6 = sp4[6];

    // rescale reciprocal off the critical path (depends only on v0.x)
    float p0f = __low2float(asbf2(v0.x));
    float rp0 = 1.f;
    if (RESCALE) rp0 = __frcp_rn(p0f);

    __nv_bfloat162 z  = __floats2bfloat162_rn(0.f, 0.f);
    __nv_bfloat162 a0 = z, a1 = z, a2 = z, a3 = z;

    a0 = __hfma2(asbf2(v0.x), et2[0],  a0);
    a1 = __hfma2(asbf2(v0.y), et2[1],  a1);
    a2 = __hfma2(asbf2(v0.z), et2[2],  a2);
    a3 = __hfma2(asbf2(v0.w), et2[3],  a3);
    a0 = __hfma2(asbf2(v1.x), et2[4],  a0);
    a1 = __hfma2(asbf2(v1.y), et2[5],  a1);
    a2 = __hfma2(asbf2(v1.z), et2[6],  a2);
    a3 = __hfma2(asbf2(v1.w), et2[7],  a3);
    a0 = __hfma2(asbf2(v2.x), et2[8],  a0);
    a1 = __hfma2(asbf2(v2.y), et2[9],  a1);
    a2 = __hfma2(asbf2(v2.z), et2[10], a2);
    a3 = __hfma2(asbf2(v2.w), et2[11], a3);
    a0 = __hfma2(asbf2(v3.x), et2[12], a0);
    a1 = __hfma2(asbf2(v3.y), et2[13], a1);
    a2 = __hfma2(asbf2(v3.z), et2[14], a2);
    a3 = __hfma2(asbf2(v3.w), et2[15], a3);
    a0 = __hfma2(asbf2(v4.x), et2[16], a0);
    a1 = __hfma2(asbf2(v4.y), et2[17], a1);
    a2 = __hfma2(asbf2(v4.z), et2[18], a2);
    a3 = __hfma2(asbf2(v4.w), et2[19], a3);
    a0 = __hfma2(asbf2(v5.x), et2[20], a0);
    a1 = __hfma2(asbf2(v5.y), et2[21], a1);
    a2 = __hfma2(asbf2(v5.z), et2[22], a2);
    a3 = __hfma2(asbf2(v5.w), et2[23], a3);
    a0 = __hfma2(asbf2(v6.x), et2[24], a0);
    a1 = __hfma2(asbf2(v6.y), et2[25], a1);
    a2 = __hfma2(asbf2(v6.z), et2[26], a2);
    a3 = __hfma2(asbf2(v6.w), et2[27], a3);

    a0 = __hadd2(a0, a1);
    a2 = __hadd2(a2, a3);
    a0 = __hadd2(a0, a2);
    float2 sf = __bfloat1622float2(a0);
    float  q  = (sf.x + sf.y) * ef;

    q = m ? q : pj;                 // masked step: carry previous partition

    if (RESCALE) {
        q *= rp0;
        offset += __logf(p0f);      // off critical path
    }

    pj = q;
    if (act) ((__nv_bfloat16*)dst)[j] = __float2bfloat16(q);

    // rotate feat pipeline
    ef = ef_next; fr1 = fr2; fr2 = fr3; fr3 = frN;

    __syncthreads();                // BAR.SYNC 0, nw=2 -> ~7 cyc, drains STS
}

__global__ void __launch_bounds__(NTHR, 1)
crf_kernel(const float* __restrict__ feats,
           const int*   __restrict__ mask,
           const int*   __restrict__ tags,
           const float* __restrict__ trans,
           float*       __restrict__ out)
{
    const int b    = blockIdx.x;
    const int j    = threadIdx.x;
    const int lane = j & 31;
    const int wid  = j >> 5;
    const bool act = (j < NTAG);

    __shared__ __align__(16) __nv_bfloat162 spA[NPAIR];
    __shared__ __align__(16) __nv_bfloat162 spB[NPAIR];
    __shared__ float s_fwd;
    __shared__ float s_acc[2];
    __shared__ int   s_len[2];
    __shared__ int   s_mask[SEQ];
    __shared__ int   s_tags[SEQ];
    __shared__ bool  s_last;
    __shared__ float s_red2[2];

    const float* fb = feats + (long long)b * SEQ * NTAG;
    const int*   mb = mask  + b * SEQ;
    const int*   tb = tags  + b * SEQ;

    // preload mask + tags for this row
    for (int t = j; t < SEQ; t += NTHR) { s_mask[t] = mb[t]; s_tags[t] = tb[t]; }

    // exp(transitions) column j as bf162 pairs (thread j owns next-tag j)
    __nv_bfloat162 et2[NPAIR];
#pragma unroll
    for (int k = 0; k < NPAIR; k++) et2[k] = __floats2bfloat162_rn(0.f, 0.f);
    if (act) {
#pragma unroll
        for (int k = 0; k < 25; k++) {
            float e0 = __expf(trans[(2 * k)     * NTAG + j]);
            float e1 = __expf(trans[(2 * k + 1) * NTAG + j]);
            et2[k] = __floats2bfloat162_rn(e0, e1);
        }
    }

    // t = 0: normalize by partition0[tag 0] (per-thread computable, no reduction)
    const float off0   = fb[0] + trans[TSTART * NTAG + 0];
    float       offset = off0;
    float pj = 0.f;
    if (act) pj = __expf(fb[j] + trans[TSTART * NTAG + j] - off0);
    if (j < 2 * NPAIR) {
        ((__nv_bfloat16*)spA)[j] = __float2bfloat16(act ? pj : 0.f);
        ((__nv_bfloat16*)spB)[j] = __float2bfloat16(0.f);   // zero pads once
    }

    // feat pipeline: ef = exp(feat(1)); fr1..fr3 = raw feats(2..4)
    float ef = 1.f, fr1 = 0.f, fr2 = 0.f, fr3 = 0.f;
    if (act) {
        ef  = __expf(fb[1 * NTAG + j]);
        fr1 = fb[2 * NTAG + j];
        fr2 = fb[3 * NTAG + j];
        fr3 = fb[4 * NTAG + j];
    }
    __syncthreads();

    // groups of 4 steps: t = 1..508, rescale on the 4th of each group
    for (int t = 1; t <= SEQ - 4; t += 4) {
        fwd_step<false>(t,     j, act, spA, spB, et2, ef, fr1, fr2, fr3, pj, offset, fb, s_mask);
        fwd_step<false>(t + 1, j, act, spB, spA, et2, ef, fr1, fr2, fr3, pj, offset, fb, s_mask);
        fwd_step<false>(t + 2, j, act, spA, spB, et2, ef, fr1, fr2, fr3, pj, offset, fb, s_mask);
        fwd_step<true >(t + 3, j, act, spB, spA, et2, ef, fr1, fr2, fr3, pj, offset, fb, s_mask);
    }
    // tail: t = 509, 510, 511 (no rescale)
    fwd_step<false>(SEQ - 3, j, act, spA, spB, et2, ef, fr1, fr2, fr3, pj, offset, fb, s_mask);
    fwd_step<false>(SEQ - 2, j, act, spB, spA, et2, ef, fr1, fr2, fr3, pj, offset, fb, s_mask);
    fwd_step<false>(SEQ - 1, j, act, spA, spB, et2, ef, fr1, fr2, fr3, pj, offset, fb, s_mask);
    // final partition lives in spB

    // terminal: forward = log( sum_i p[i] * exp(trans[i,STOP]) ) + offset
    if (j == TSTOP) {
        const float4* sp4 = (const float4*)spB;
        __nv_bfloat162 z  = __floats2bfloat162_rn(0.f, 0.f);
        __nv_bfloat162 a0 = z, a1 = z, a2 = z, a3 = z;
#pragma unroll
        for (int k = 0; k < 7; k++) {
            float4 v = sp4[k];
            a0 = __hfma2(asbf2(v.x), et2[4 * k + 0], a0);
            a1 = __hfma2(asbf2(v.y), et2[4 * k + 1], a1);
            a2 = __hfma2(asbf2(v.z), et2[4 * k + 2], a2);
            a3 = __hfma2(asbf2(v.w), et2[4 * k + 3], a3);
        }
        a0 = __hadd2(a0, a1);
        a2 = __hadd2(a2, a3);
        a0 = __hadd2(a0, a2);
        float2 sf = __bfloat1622float2(a0);
        s_fwd = __logf(sf.x + sf.y) + offset;
    }

    // ---- gold score (all 64 threads, epilogue) ----
    float acc = 0.f;
    int   len = 0;
#pragma unroll
    for (int t = j; t < SEQ; t += NTHR) {
        int tag  = s_tags[t];
        int prev = (t == 0) ? TSTART : s_tags[t - 1];
        int m    = s_mask[t];
        if (m) acc += fb[t * NTAG + tag] + trans[prev * NTAG + tag];
        len += m;
    }
    acc = warpSumF(acc);
    len = warpSumI(len);
    if (lane == 0) { s_acc[wid] = acc; s_len[wid] = len; }
    __syncthreads();

    if (j == 0) {
        int   L     = s_len[0] + s_len[1];
        int   endid = s_tags[L - 1];
        float gold  = s_acc[0] + s_acc[1] + trans[endid * NTAG + TSTOP];
        g_partial[b] = s_fwd - gold;
        __threadfence();
        unsigned tk = atomicAdd(&g_ticket, 1u);
        s_last = (tk == BATCH - 1);
    }
    __syncthreads();

    // last CTA out: reduce all 64 batch values, reset ticket (graph-replay safe)
    if (s_last) {
        float v = ((volatile float*)g_partial)[j];
        v = warpSumF(v);
        if (lane == 0) s_red2[wid] = v;
        __syncthreads();
        if (j == 0) {
            out[0] = s_red2[0] + s_red2[1];
            g_ticket = 0;
        }
    }
}

extern "C" void kernel_launch(void* const* d_in, const int* in_sizes, int n_in,
                              void* d_out, int out_size)
{
    const float* feats = (const float*)d_in[0];
    const int*   mask  = (const int*)d_in[1];
    const int*   tags  = (const int*)d_in[2];
    const float* trans = (const float*)d_in[3];
    float* out = (float*)d_out;

    crf_kernel<<<BATCH, NTHR>>>(feats, mask, tags, trans, out);
}